// round 15
// baseline (speedup 1.0000x reference)
#include <cuda_runtime.h>
#include <math.h>

// ---------------- problem constants ----------------
constexpr int Bc   = 2;
constexpr int Sc   = 2048;
constexpr int HIDc = 2048;
constexpr int NHc  = 16;
constexpr int HDc  = 128;
constexpr int RDc  = 32;
constexpr int SBc  = 204;           // int(0.1 * S)
constexpr int RBc  = 204;           // int(0.1 * S)
constexpr int MBc  = 128;           // MERGE_BUDGET
constexpr int TKc  = 16;            // TOPK
constexpr int NCAND = Sc - RBc - SBc;   // 1640 candidates
constexpr int NQCH = 8;             // colreduce q-chunks

// ---------------- device scratch (static, allocation-free) ----------------
__device__ float g_q   [(size_t)Bc * NHc * Sc * HDc];    //  32 MB
__device__ float g_k   [(size_t)Bc * NHc * Sc * HDc];    //  32 MB
__device__ float g_v   [(size_t)Bc * NHc * Sc * HDc];    //  32 MB
__device__ float g_attn[(size_t)Bc * NHc * Sc * Sc];     // 512 MB
__device__ float g_outh[(size_t)Bc * Sc * HIDc];         //  32 MB
__device__ float g_colpart[(size_t)NQCH * NHc * Sc];
__device__ float g_colsum[NHc * Sc];
__device__ float g_ratio [NHc * Sc];
__device__ int   g_topidx[NHc * TKc];
__device__ float g_topval[NHc * TKc];

// ---------------- tf32 helpers ----------------
__device__ __forceinline__ unsigned f2t(float x) {
    unsigned r; asm("cvt.rna.tf32.f32 %0, %1;" : "=r"(r) : "f"(x)); return r;
}
__device__ __forceinline__ void mma8(float* c, const unsigned* a, const unsigned* b) {
    asm volatile(
        "mma.sync.aligned.m16n8k8.row.col.f32.tf32.tf32.f32 "
        "{%0,%1,%2,%3}, {%4,%5,%6,%7}, {%8,%9}, {%0,%1,%2,%3};"
        : "+f"(c[0]), "+f"(c[1]), "+f"(c[2]), "+f"(c[3])
        : "r"(a[0]), "r"(a[1]), "r"(a[2]), "r"(a[3]), "r"(b[0]), "r"(b[1]));
}

// store one 8-deep K slice (converted to tf32) into a [16][pad] tile
#define STS8(ARR, BUFI, V0, V1)                                               \
    ARR[BUFI][lkh+0][lrow]=f2t(V0.x); ARR[BUFI][lkh+1][lrow]=f2t(V0.y);       \
    ARR[BUFI][lkh+2][lrow]=f2t(V0.z); ARR[BUFI][lkh+3][lrow]=f2t(V0.w);       \
    ARR[BUFI][lkh+4][lrow]=f2t(V1.x); ARR[BUFI][lkh+5][lrow]=f2t(V1.y);       \
    ARR[BUFI][lkh+6][lrow]=f2t(V1.z); ARR[BUFI][lkh+7][lrow]=f2t(V1.w);

// warp-tile compute (4m x 4n of m16n8k8): A,B both [16][pad] k-major tiles
#define COMPUTE_TILE(ASRC, BSRC)                                              \
    _Pragma("unroll")                                                         \
    for (int ks = 0; ks < 16; ks += 8) {                                      \
        unsigned afr[4][4], bfr[4][2];                                        \
        _Pragma("unroll")                                                     \
        for (int mt = 0; mt < 4; mt++) {                                      \
            const int m0 = wm + mt*16 + ar;                                   \
            afr[mt][0] = ASRC[ks+ak][m0];                                     \
            afr[mt][1] = ASRC[ks+ak][m0+8];                                   \
            afr[mt][2] = ASRC[ks+4+ak][m0];                                   \
            afr[mt][3] = ASRC[ks+4+ak][m0+8];                                 \
        }                                                                     \
        _Pragma("unroll")                                                     \
        for (int nt = 0; nt < 4; nt++) {                                      \
            const int n0 = wn + nt*8 + ar;                                    \
            bfr[nt][0] = BSRC[ks+ak][n0];                                     \
            bfr[nt][1] = BSRC[ks+4+ak][n0];                                   \
        }                                                                     \
        _Pragma("unroll")                                                     \
        for (int mt = 0; mt < 4; mt++)                                        \
            _Pragma("unroll")                                                 \
            for (int nt = 0; nt < 4; nt++)                                    \
                mma8(acc[mt][nt], afr[mt], bfr[nt]);                          \
    }

// ============ 128M x 256N TF32 GEMM core (dynamic smem, dbuf) ============
// As: [2][16][136], Bs: [2][16][264]. 8 warps, warp tile 64x64.
constexpr int APAD = 136, BPAD = 264;
constexpr int SMEMDYN = (2 * 16 * APAD + 2 * 16 * BPAD) * 4;

#define GEMM256_PROLOG_AND_LOOP(...)                                          \
    extern __shared__ unsigned smraw[];                                       \
    unsigned (*As)[16][APAD] = (unsigned(*)[16][APAD])smraw;                  \
    unsigned (*Bs)[16][BPAD] = (unsigned(*)[16][BPAD])(smraw + 2*16*APAD);    \
    const int tid = threadIdx.x, lane = tid & 31, w = tid >> 5;               \
    const int bm = blockIdx.y * 128, bn = blockIdx.x * 256;                   \
    const int wm = (w >> 2) * 64, wn = (w & 3) * 64;                          \
    const int lrow = tid & 127, lkh = (tid >> 7) * 8;                         \
    const int ar = lane >> 2, ak = lane & 3;                                  \
    const float* Ap  = A  + (size_t)(bm + lrow) * K + lkh;                    \
    const float* Bp0 = Bm + (size_t)(bn + lrow) * K + lkh;                    \
    const float* Bp1 = Bm + (size_t)(bn + lrow + 128) * K + lkh;              \
    float acc[4][8][4];                                                       \
    _Pragma("unroll")                                                         \
    for (int mt = 0; mt < 4; mt++)                                            \
        _Pragma("unroll")                                                     \
        for (int nt = 0; nt < 8; nt++)                                        \
            _Pragma("unroll")                                                 \
            for (int i = 0; i < 4; i++) acc[mt][nt][i] = 0.f;                 \
    float4 pa0 = *(const float4*)Ap,  pa1 = *(const float4*)(Ap + 4);         \
    float4 pb0 = *(const float4*)Bp0, pb1 = *(const float4*)(Bp0 + 4);        \
    float4 pc0 = *(const float4*)Bp1, pc1 = *(const float4*)(Bp1 + 4);        \
    {                                                                         \
        STS8(As, 0, pa0, pa1);                                                \
        STS8(Bs, 0, pb0, pb1);                                                \
        Bs[0][lkh+0][lrow+128]=f2t(pc0.x); Bs[0][lkh+1][lrow+128]=f2t(pc0.y); \
        Bs[0][lkh+2][lrow+128]=f2t(pc0.z); Bs[0][lkh+3][lrow+128]=f2t(pc0.w); \
        Bs[0][lkh+4][lrow+128]=f2t(pc1.x); Bs[0][lkh+5][lrow+128]=f2t(pc1.y); \
        Bs[0][lkh+6][lrow+128]=f2t(pc1.z); Bs[0][lkh+7][lrow+128]=f2t(pc1.w); \
    }                                                                         \
    __syncthreads();                                                          \
    int buf = 0;                                                              \
    for (int k0 = 0; k0 < K; k0 += 16) {                                      \
        const bool more = (k0 + 16 < K);                                      \
        if (more) {                                                           \
            pa0 = *(const float4*)(Ap  + k0 + 16); pa1 = *(const float4*)(Ap  + k0 + 20); \
            pb0 = *(const float4*)(Bp0 + k0 + 16); pb1 = *(const float4*)(Bp0 + k0 + 20); \
            pc0 = *(const float4*)(Bp1 + k0 + 16); pc1 = *(const float4*)(Bp1 + k0 + 20); \
        }                                                                     \
        _Pragma("unroll")                                                     \
        for (int ks = 0; ks < 16; ks += 8) {                                  \
            unsigned afr[4][4], bfr[8][2];                                    \
            _Pragma("unroll")                                                 \
            for (int mt = 0; mt < 4; mt++) {                                  \
                const int m0 = wm + mt*16 + ar;                               \
                afr[mt][0] = As[buf][ks+ak][m0];                              \
                afr[mt][1] = As[buf][ks+ak][m0+8];                            \
                afr[mt][2] = As[buf][ks+4+ak][m0];                            \
                afr[mt][3] = As[buf][ks+4+ak][m0+8];                          \
            }                                                                 \
            _Pragma("unroll")                                                 \
            for (int nt = 0; nt < 8; nt++) {                                  \
                const int n0 = wn + nt*8 + ar;                                \
                bfr[nt][0] = Bs[buf][ks+ak][n0];                              \
                bfr[nt][1] = Bs[buf][ks+4+ak][n0];                            \
            }                                                                 \
            _Pragma("unroll")                                                 \
            for (int mt = 0; mt < 4; mt++)                                    \
                _Pragma("unroll")                                             \
                for (int nt = 0; nt < 8; nt++)                                \
                    mma8(acc[mt][nt], afr[mt], bfr[nt]);                      \
        }                                                                     \
        if (more) {                                                           \
            const int nb = buf ^ 1;                                           \
            STS8(As, nb, pa0, pa1);                                           \
            STS8(Bs, nb, pb0, pb1);                                           \
            Bs[nb][lkh+0][lrow+128]=f2t(pc0.x); Bs[nb][lkh+1][lrow+128]=f2t(pc0.y); \
            Bs[nb][lkh+2][lrow+128]=f2t(pc0.z); Bs[nb][lkh+3][lrow+128]=f2t(pc0.w); \
            Bs[nb][lkh+4][lrow+128]=f2t(pc1.x); Bs[nb][lkh+5][lrow+128]=f2t(pc1.y); \
            Bs[nb][lkh+6][lrow+128]=f2t(pc1.z); Bs[nb][lkh+7][lrow+128]=f2t(pc1.w); \
        }                                                                     \
        __syncthreads();                                                      \
        buf ^= 1;                                                             \
    }                                                                         \
    __VA_ARGS__

// ====== QKV GEMM (128x256, 256t) + fused bias + RoPE + per-head scatter =====
__global__ __launch_bounds__(256) void qkv_gemm_tc(
    const float* __restrict__ A, const float* __restrict__ Bm,
    const float* __restrict__ bias, const int* __restrict__ pos,
    float* __restrict__ qb, float* __restrict__ kb, float* __restrict__ vb)
{
    constexpr int K = HIDc;
    GEMM256_PROLOG_AND_LOOP(
    {
        const int ac2 = (lane & 3) * 2;
        const int cb = bn + wn;                 // 64-aligned chunk base
        const int h = cb / 384;
        const int rm = cb - h * 384;            // 0,64,...,320
        const int sel = rm >> 7;                // 0=q,1=k,2=v (const per chunk)
        const int dbase = rm & 127;             // 0 or 64
        float* basep = (sel == 0) ? qb : (sel == 1) ? kb : vb;
        const bool dorope = (sel < 2) && (dbase == 0);

        float bcol[8][2];
        _Pragma("unroll")
        for (int nt = 0; nt < 8; nt++) {
            bcol[nt][0] = bias[cb + nt * 8 + ac2];
            bcol[nt][1] = bias[cb + nt * 8 + ac2 + 1];
        }

        _Pragma("unroll")
        for (int mt = 0; mt < 4; mt++) {
            const int r0 = bm + wm + mt * 16 + ar;
            const int bb = r0 >> 11;
            const int s  = r0 & 2047;

            float vout[8][4];
            _Pragma("unroll")
            for (int nt = 0; nt < 8; nt++) {
                vout[nt][0] = acc[mt][nt][0] + bcol[nt][0];
                vout[nt][1] = acc[mt][nt][1] + bcol[nt][1];
                vout[nt][2] = acc[mt][nt][2] + bcol[nt][0];
                vout[nt][3] = acc[mt][nt][3] + bcol[nt][1];
            }

            if (dorope) {
                const float t0 = (float)pos[bb * Sc + s];
                const float t8 = (float)pos[bb * Sc + s + 8];
                _Pragma("unroll")
                for (int nt = 0; nt < 2; nt++) {
                    _Pragma("unroll")
                    for (int i = 0; i < 4; i++) {
                        const int d = nt * 8 + ac2 + (i & 1);   // < 16
                        const float invf =
                            exp2f(-((float)d * (1.0f / 16.0f)) * 13.28771237954945f);
                        const float t = (i >> 1) ? t8 : t0;
                        float sn, cs;
                        sincosf(t * invf, &sn, &cs);
                        const float Av = vout[nt][i];
                        const float Bv = vout[nt + 2][i];
                        vout[nt][i]     = Av * cs - Bv * sn;
                        vout[nt + 2][i] = Bv * cs + Av * sn;
                    }
                }
            }

            _Pragma("unroll")
            for (int nt = 0; nt < 8; nt++) {
                const int d0 = dbase + nt * 8 + ac2;
                float* dst = basep + (((size_t)(bb * NHc + h) * Sc + s) * HDc + d0);
                *(float2*)dst = make_float2(vout[nt][0], vout[nt][1]);
                *(float2*)(dst + (size_t)8 * HDc) = make_float2(vout[nt][2], vout[nt][3]);
            }
        }
    })
}

// ================= dense GEMM (128x256), plain output =======================
__global__ __launch_bounds__(256) void gemm_tn_tc256(
    const float* __restrict__ A, const float* __restrict__ Bm,
    const float* __restrict__ bias, float* __restrict__ C,
    int M, int N, int K)
{
    GEMM256_PROLOG_AND_LOOP(
    {
        const int ac2 = (lane & 3) * 2;
        _Pragma("unroll")
        for (int nt = 0; nt < 8; nt++) {
            const int col = bn + wn + nt * 8 + ac2;
            const float b0 = bias[col];
            const float b1 = bias[col + 1];
            _Pragma("unroll")
            for (int mt = 0; mt < 4; mt++) {
                const int r0 = bm + wm + mt * 16 + ar;
                *(float2*)&C[(size_t)r0 * N + col] =
                    make_float2(acc[mt][nt][0] + b0, acc[mt][nt][1] + b1);
                *(float2*)&C[(size_t)(r0 + 8) * N + col] =
                    make_float2(acc[mt][nt][2] + b0, acc[mt][nt][3] + b1);
            }
        }
    })
}

// ================= scores = scale * Q K^T (TF32, causal tiles, dbuf) =========
__global__ __launch_bounds__(256) void scores_tc()
{
    if (blockIdx.x > blockIdx.y) return;
    constexpr float SCALE = 0.08838834764831845f;  // 1/sqrt(128)
    __shared__ unsigned As[2][16][APAD];
    __shared__ unsigned Bs[2][16][APAD];

    const int tid = threadIdx.x, lane = tid & 31, w = tid >> 5;
    const int bh = blockIdx.z;
    const int bm = blockIdx.y * 128, bn = blockIdx.x * 128;
    const int wm = (w >> 2) * 64, wn = (w & 3) * 32;
    const int lrow = tid & 127, lkh = (tid >> 7) * 8;
    const int ar = lane >> 2, ak = lane & 3;

    const float* Ap = g_q + (size_t)bh * Sc * HDc + (size_t)(bm + lrow) * HDc + lkh;
    const float* Bp = g_k + (size_t)bh * Sc * HDc + (size_t)(bn + lrow) * HDc + lkh;
    float* C = g_attn + (size_t)bh * Sc * Sc;

    float acc[4][4][4];
#pragma unroll
    for (int mt = 0; mt < 4; mt++)
#pragma unroll
        for (int nt = 0; nt < 4; nt++)
#pragma unroll
            for (int i = 0; i < 4; i++) acc[mt][nt][i] = 0.f;

    float4 pa0 = *(const float4*)Ap, pa1 = *(const float4*)(Ap + 4);
    float4 pb0 = *(const float4*)Bp, pb1 = *(const float4*)(Bp + 4);
    STS8(As, 0, pa0, pa1);
    STS8(Bs, 0, pb0, pb1);
    __syncthreads();

    int buf = 0;
    for (int k0 = 0; k0 < HDc; k0 += 16) {
        const bool more = (k0 + 16 < HDc);
        if (more) {
            pa0 = *(const float4*)(Ap + k0 + 16); pa1 = *(const float4*)(Ap + k0 + 20);
            pb0 = *(const float4*)(Bp + k0 + 16); pb1 = *(const float4*)(Bp + k0 + 20);
        }
        COMPUTE_TILE(As[buf], Bs[buf]);
        if (more) {
            const int nb = buf ^ 1;
            STS8(As, nb, pa0, pa1);
            STS8(Bs, nb, pb0, pb1);
        }
        __syncthreads();
        buf ^= 1;
    }

    const int ac2 = (lane & 3) * 2;
#pragma unroll
    for (int nt = 0; nt < 4; nt++) {
        const int col = bn + wn + nt * 8 + ac2;
#pragma unroll
        for (int mt = 0; mt < 4; mt++) {
            const int r0 = bm + wm + mt * 16 + ar;
            *(float2*)&C[(size_t)r0 * Sc + col] =
                make_float2(acc[mt][nt][0] * SCALE, acc[mt][nt][1] * SCALE);
            *(float2*)&C[(size_t)(r0 + 8) * Sc + col] =
                make_float2(acc[mt][nt][2] * SCALE, acc[mt][nt][3] * SCALE);
        }
    }
}

// ---------------- causal row softmax, float4 over valid groups ----------------
__global__ __launch_bounds__(256) void softmax_kernel(const float* __restrict__ amask)
{
    const int row = blockIdx.x;
    const int q = row & (Sc - 1);
    const int b = row >> 15;               // / (NHc*Sc)
    float* ap = g_attn + (size_t)row * Sc;
    const float* mp = amask + (size_t)b * Sc;

    const int tid = threadIdx.x, lane = tid & 31, w = tid >> 5;
    __shared__ float sred[8];

    const int nv = (q >> 2) + 1;           // float4 groups covering [0, q]
    float4 x[2];
    float lm = -3.4e38f;
#pragma unroll
    for (int it = 0; it < 2; it++) {
        const int g = tid + it * 256;
        if (g < nv) {
            float4 v = *(const float4*)(ap + g * 4);
            float4 m = *(const float4*)(mp + g * 4);
            const int k = g * 4;
            v.x = (k + 0 <= q) ? v.x + m.x : -3.4e38f;
            v.y = (k + 1 <= q) ? v.y + m.y : -3.4e38f;
            v.z = (k + 2 <= q) ? v.z + m.z : -3.4e38f;
            v.w = (k + 3 <= q) ? v.w + m.w : -3.4e38f;
            x[it] = v;
            lm = fmaxf(lm, fmaxf(fmaxf(v.x, v.y), fmaxf(v.z, v.w)));
        } else {
            x[it] = make_float4(-3.4e38f, -3.4e38f, -3.4e38f, -3.4e38f);
        }
    }
#pragma unroll
    for (int o = 16; o > 0; o >>= 1) lm = fmaxf(lm, __shfl_xor_sync(0xffffffffu, lm, o));
    if (lane == 0) sred[w] = lm;
    __syncthreads();
    float m = sred[0];
#pragma unroll
    for (int i = 1; i < 8; i++) m = fmaxf(m, sred[i]);
    __syncthreads();

    float ls = 0.f;
#pragma unroll
    for (int it = 0; it < 2; it++) {
        const int g = tid + it * 256;
        if (g < nv) {
            float4 v = x[it];
            v.x = __expf(v.x - m); v.y = __expf(v.y - m);
            v.z = __expf(v.z - m); v.w = __expf(v.w - m);
            x[it] = v;
            ls += v.x + v.y + v.z + v.w;
        }
    }
#pragma unroll
    for (int o = 16; o > 0; o >>= 1) ls += __shfl_xor_sync(0xffffffffu, ls, o);
    if (lane == 0) sred[w] = ls;
    __syncthreads();
    float s = 0.f;
#pragma unroll
    for (int i = 0; i < 8; i++) s += sred[i];
    const float inv = 1.0f / s;

#pragma unroll
    for (int it = 0; it < 2; it++) {
        const int g = tid + it * 256;
        if (g < nv) {
            float4 v = x[it];
            *(float4*)(ap + g * 4) =
                make_float4(v.x * inv, v.y * inv, v.z * inv, v.w * inv);
        }
    }
}

// -------- column-sum partials per q-chunk, float4 per thread (deterministic) --
__global__ void colpart_kernel()
{
    const int k0 = (blockIdx.x * 256 + threadIdx.x) * 4;   // 4 consecutive cols
    const int h = blockIdx.y;
    const int z = blockIdx.z;
    const int qlo = z * 256, qhi = qlo + 256;
    const bool rz = (z == NQCH - 1);

    // boundary band [max(qlo,k0), min(qhi,k0+4)): per-element causal predicates
    int q1s = (k0 > qlo) ? k0 : qlo;  if (q1s > qhi) q1s = qhi;
    int q1e = (k0 + 4 < qhi) ? (k0 + 4) : qhi;  if (q1e < q1s) q1e = q1s;
    // main band [max(qlo, k0+4), qhi): all 4 elements valid
    int q2s = (k0 + 4 > qlo) ? (k0 + 4) : qlo;  if (q2s > qhi) q2s = qhi;

    float4 s = make_float4(0.f, 0.f, 0.f, 0.f);
    float4 r = make_float4(0.f, 0.f, 0.f, 0.f);
    for (int b = 0; b < Bc; b++) {
        const float* ap = g_attn + ((size_t)(b * NHc + h)) * Sc * Sc + k0;
        for (int q = q1s; q < q1e; q++) {
            float4 a = *(const float4*)(ap + (size_t)q * Sc);
            a.x = (q >= k0 + 0) ? a.x : 0.f;
            a.y = (q >= k0 + 1) ? a.y : 0.f;
            a.z = (q >= k0 + 2) ? a.z : 0.f;
            a.w = (q >= k0 + 3) ? a.w : 0.f;
            s.x += a.x; s.y += a.y; s.z += a.z; s.w += a.w;
            if (rz && q >= Sc - MBc) { r.x += a.x; r.y += a.y; r.z += a.z; r.w += a.w; }
        }
#pragma unroll 4
        for (int q = q2s; q < qhi; q++) {
            float4 a = *(const float4*)(ap + (size_t)q * Sc);
            s.x += a.x; s.y += a.y; s.z += a.z; s.w += a.w;
            if (rz && q >= Sc - MBc) { r.x += a.x; r.y += a.y; r.z += a.z; r.w += a.w; }
        }
    }
    *(float4*)&g_colpart[((size_t)z * NHc + h) * Sc + k0] = s;
    if (rz) *(float4*)&g_ratio[h * Sc + k0] = r;
}

__global__ void colsumfin_kernel()
{
    const int k0 = (blockIdx.x * 256 + threadIdx.x) * 4;
    const int h = blockIdx.y;
    float4 s = make_float4(0.f, 0.f, 0.f, 0.f);
#pragma unroll
    for (int z = 0; z < NQCH; z++) {
        float4 p = *(const float4*)&g_colpart[((size_t)z * NHc + h) * Sc + k0];
        s.x += p.x; s.y += p.y; s.z += p.z; s.w += p.w;
    }
    *(float4*)&g_colsum[h * Sc + k0] = s;
}

// ---------------- top-k per head (jax tie-break: lowest index) ----------------
__global__ __launch_bounds__(256) void topk_kernel()
{
    const int h = blockIdx.x, tid = threadIdx.x;
    __shared__ float tv[NCAND];
    __shared__ float rv[256];
    __shared__ int   ri[256];

    for (int i = tid; i < NCAND; i += 256) tv[i] = g_colsum[h * Sc + SBc + i];
    __syncthreads();

    for (int r = 0; r < TKc; r++) {
        float bv = -1e30f; int bi = NCAND;
        for (int i = tid; i < NCAND; i += 256) {
            float v = tv[i];
            if (v > bv) { bv = v; bi = i; }
        }
        rv[tid] = bv; ri[tid] = bi;
        __syncthreads();
        for (int st = 128; st > 0; st >>= 1) {
            if (tid < st) {
                if (rv[tid + st] > rv[tid] ||
                    (rv[tid + st] == rv[tid] && ri[tid + st] < ri[tid])) {
                    rv[tid] = rv[tid + st]; ri[tid] = ri[tid + st];
                }
            }
            __syncthreads();
        }
        if (tid == 0) {
            const int gi = ri[0] + SBc;
            g_topidx[h * TKc + r] = gi;
            g_topval[h * TKc + r] = g_ratio[h * Sc + gi] * (1.0f / MBc);
            tv[ri[0]] = -1e30f;
        }
        __syncthreads();
    }
}

// ---------------- v[b,h,SB,:] = sum_j v[b,h,idx_j,:] * val_j ----------------
__global__ void vupdate_kernel()
{
    const int bh = blockIdx.x;
    const int h  = bh % NHc;
    const int d  = threadIdx.x;
    float* vp = g_v + (size_t)bh * Sc * HDc;
    float acc = 0.f;
#pragma unroll
    for (int j = 0; j < TKc; j++)
        acc += vp[(size_t)g_topidx[h * TKc + j] * HDc + d] * g_topval[h * TKc + j];
    vp[(size_t)SBc * HDc + d] = acc;
}

// ================= out = attn @ v (TF32, causal, dbuf), scatter ==============
__global__ __launch_bounds__(256) void attnv_tc()
{
    __shared__ unsigned As[2][16][APAD]; // [k][m]
    __shared__ unsigned Vs[2][128][20];  // [n][k]

    const int tid = threadIdx.x, lane = tid & 31, w = tid >> 5;
    const int bh = blockIdx.y;
    const int bm = blockIdx.x * 128;
    const int wm = (w >> 2) * 64, wn = (w & 3) * 32;
    const int ar = lane >> 2, ak = lane & 3;

    const float* attn = g_attn + (size_t)bh * Sc * Sc;
    const float* vp   = g_v    + (size_t)bh * Sc * HDc;

    const int lrow = tid & 127, lkh = (tid >> 7) * 8;
    const int q_l = bm + lrow;
    const float* arow = attn + (size_t)q_l * Sc;
    const int vk = tid & 15, vn = (tid >> 4) * 8;

    float acc[4][4][4];
#pragma unroll
    for (int mt = 0; mt < 4; mt++)
#pragma unroll
        for (int nt = 0; nt < 4; nt++)
#pragma unroll
            for (int i = 0; i < 4; i++) acc[mt][nt][i] = 0.f;

    const int kend = bm + 128;

#define STS_A_MASKED(BUFI, V0, V1, KB)                                        \
    As[BUFI][lkh+0][lrow] = ((KB)+0 <= q_l) ? f2t(V0.x) : 0u;                 \
    As[BUFI][lkh+1][lrow] = ((KB)+1 <= q_l) ? f2t(V0.y) : 0u;                 \
    As[BUFI][lkh+2][lrow] = ((KB)+2 <= q_l) ? f2t(V0.z) : 0u;                 \
    As[BUFI][lkh+3][lrow] = ((KB)+3 <= q_l) ? f2t(V0.w) : 0u;                 \
    As[BUFI][lkh+4][lrow] = ((KB)+4 <= q_l) ? f2t(V1.x) : 0u;                 \
    As[BUFI][lkh+5][lrow] = ((KB)+5 <= q_l) ? f2t(V1.y) : 0u;                 \
    As[BUFI][lkh+6][lrow] = ((KB)+6 <= q_l) ? f2t(V1.z) : 0u;                 \
    As[BUFI][lkh+7][lrow] = ((KB)+7 <= q_l) ? f2t(V1.w) : 0u;

#define STS_V(BUFI, V0, V1)                                                   \
    Vs[BUFI][vn+0][vk]=f2t(V0.x); Vs[BUFI][vn+1][vk]=f2t(V0.y);               \
    Vs[BUFI][vn+2][vk]=f2t(V0.z); Vs[BUFI][vn+3][vk]=f2t(V0.w);               \
    Vs[BUFI][vn+4][vk]=f2t(V1.x); Vs[BUFI][vn+5][vk]=f2t(V1.y);               \
    Vs[BUFI][vn+6][vk]=f2t(V1.z); Vs[BUFI][vn+7][vk]=f2t(V1.w);

    // prologue: tile k0 = 0
    {
        float4 a0v = *(const float4*)(arow + lkh);
        float4 a1v = *(const float4*)(arow + lkh + 4);
        STS_A_MASKED(0, a0v, a1v, lkh);
        const float* vr = vp + (size_t)vk * HDc + vn;
        float4 v0 = *(const float4*)vr, v1 = *(const float4*)(vr + 4);
        STS_V(0, v0, v1);
    }
    __syncthreads();

    int buf = 0;
    for (int k0 = 0; k0 < kend; k0 += 16) {
        const bool more = (k0 + 16 < kend);
        float4 a0v, a1v, v0, v1;
        if (more) {
            a0v = *(const float4*)(arow + k0 + 16 + lkh);
            a1v = *(const float4*)(arow + k0 + 20 + lkh);
            const float* vr = vp + (size_t)(k0 + 16 + vk) * HDc + vn;
            v0 = *(const float4*)vr; v1 = *(const float4*)(vr + 4);
        }

#pragma unroll
        for (int ks = 0; ks < 16; ks += 8) {
            unsigned afr[4][4], bfr[4][2];
#pragma unroll
            for (int mt = 0; mt < 4; mt++) {
                const int m0 = wm + mt * 16 + ar;
                afr[mt][0] = As[buf][ks+ak][m0];
                afr[mt][1] = As[buf][ks+ak][m0+8];
                afr[mt][2] = As[buf][ks+4+ak][m0];
                afr[mt][3] = As[buf][ks+4+ak][m0+8];
            }
#pragma unroll
            for (int nt = 0; nt < 4; nt++) {
                const int n0 = wn + nt * 8 + ar;
                bfr[nt][0] = Vs[buf][n0][ks+ak];
                bfr[nt][1] = Vs[buf][n0][ks+4+ak];
            }
#pragma unroll
            for (int mt = 0; mt < 4; mt++)
#pragma unroll
                for (int nt = 0; nt < 4; nt++) mma8(acc[mt][nt], afr[mt], bfr[nt]);
        }

        if (more) {
            const int nb = buf ^ 1;
            const int kb2 = k0 + 16 + lkh;
            STS_A_MASKED(nb, a0v, a1v, kb2);
            STS_V(nb, v0, v1);
        }
        __syncthreads();
        buf ^= 1;
    }

    const int b = bh >> 4, h = bh & 15;
    const int ac2 = (lane & 3) * 2;
#pragma unroll
    for (int nt = 0; nt < 4; nt++) {
        const int col = h * HDc + wn + nt * 8 + ac2;
#pragma unroll
        for (int mt = 0; mt < 4; mt++) {
            const int q = bm + wm + mt * 16 + ar;
            *(float2*)&g_outh[((size_t)(b * Sc + q)) * HIDc + col] =
                make_float2(acc[mt][nt][0], acc[mt][nt][1]);
            *(float2*)&g_outh[((size_t)(b * Sc + q + 8)) * HIDc + col] =
                make_float2(acc[mt][nt][2], acc[mt][nt][3]);
        }
    }
#undef STS_A_MASKED
#undef STS_V
}

// ---------------- launch ----------------
extern "C" void kernel_launch(void* const* d_in, const int* in_sizes, int n_in,
                              void* d_out, int out_size)
{
    (void)in_sizes; (void)n_in; (void)out_size;
    const float* hs    = (const float*)d_in[0];
    const float* amask = (const float*)d_in[1];
    const int*   pos   = (const int*)  d_in[2];
    const float* Wqkv  = (const float*)d_in[3];
    const float* bqkv  = (const float*)d_in[4];
    const float* Wd    = (const float*)d_in[5];
    const float* bd    = (const float*)d_in[6];
    float* out = (float*)d_out;

    void *p_q = nullptr, *p_k = nullptr, *p_v = nullptr, *p_outh = nullptr;
    cudaGetSymbolAddress(&p_q, g_q);
    cudaGetSymbolAddress(&p_k, g_k);
    cudaGetSymbolAddress(&p_v, g_v);
    cudaGetSymbolAddress(&p_outh, g_outh);

    cudaFuncSetAttribute(qkv_gemm_tc,
                         cudaFuncAttributeMaxDynamicSharedMemorySize, SMEMDYN);
    cudaFuncSetAttribute(gemm_tn_tc256,
                         cudaFuncAttributeMaxDynamicSharedMemorySize, SMEMDYN);

    // 1. QKV projection + fused bias/RoPE + per-head scatter (TF32, 128x256)
    qkv_gemm_tc<<<dim3(3 * HIDc / 256, (Bc * Sc) / 128), 256, SMEMDYN>>>(
        hs, Wqkv, bqkv, pos, (float*)p_q, (float*)p_k, (float*)p_v);

    // 2. scaled QK^T (causal tiles, TF32, dbuf)
    scores_tc<<<dim3(Sc / 128, Sc / 128, Bc * NHc), 256>>>();

    // 3. row softmax (vectorized, causal groups only)
    softmax_kernel<<<Bc * NHc * Sc, 256>>>(amask);

    // 4a/4b. column statistics: float4 per-chunk partials + fixed-order sum
    colpart_kernel<<<dim3(Sc / 1024, NHc, NQCH), 256>>>();
    colsumfin_kernel<<<dim3(Sc / 1024, NHc), 256>>>();

    // 5. per-head top-16
    topk_kernel<<<NHc, 256>>>();

    // 6. merged row write into v
    vupdate_kernel<<<Bc * NHc, HDc>>>();

    // 7. attn @ v (TF32, dbuf)
    attnv_tc<<<dim3(Sc / 128, Bc * NHc), 256>>>();

    // 8. dense projection (TF32, 128x256)
    gemm_tn_tc256<<<dim3(HIDc / 256, (Bc * Sc) / 128), 256, SMEMDYN>>>(
        (const float*)p_outh, Wd, bd, out, Bc * Sc, HIDc, HIDc);
}

// round 16
// speedup vs baseline: 1.0019x; 1.0019x over previous
#include <cuda_runtime.h>
#include <math.h>

// ---------------- problem constants ----------------
constexpr int Bc   = 2;
constexpr int Sc   = 2048;
constexpr int HIDc = 2048;
constexpr int NHc  = 16;
constexpr int HDc  = 128;
constexpr int RDc  = 32;
constexpr int SBc  = 204;           // int(0.1 * S)
constexpr int RBc  = 204;           // int(0.1 * S)
constexpr int MBc  = 128;           // MERGE_BUDGET
constexpr int TKc  = 16;            // TOPK
constexpr int NCAND = Sc - RBc - SBc;   // 1640 candidates
constexpr int NQCH = 8;             // colreduce q-chunks

// ---------------- device scratch (static, allocation-free) ----------------
__device__ float g_q   [(size_t)Bc * NHc * Sc * HDc];    //  32 MB
__device__ float g_k   [(size_t)Bc * NHc * Sc * HDc];    //  32 MB
__device__ float g_v   [(size_t)Bc * NHc * Sc * HDc];    //  32 MB
__device__ float g_attn[(size_t)Bc * NHc * Sc * Sc];     // 512 MB
__device__ float g_outh[(size_t)Bc * Sc * HIDc];         //  32 MB
__device__ float g_colpart[(size_t)NQCH * NHc * Sc];
__device__ float g_colsum[NHc * Sc];
__device__ float g_ratio [NHc * Sc];
__device__ int   g_topidx[NHc * TKc];
__device__ float g_topval[NHc * TKc];

// ---------------- tf32 helpers ----------------
__device__ __forceinline__ unsigned f2t(float x) {
    unsigned r; asm("cvt.rna.tf32.f32 %0, %1;" : "=r"(r) : "f"(x)); return r;
}
__device__ __forceinline__ void mma8(float* c, const unsigned* a, const unsigned* b) {
    asm volatile(
        "mma.sync.aligned.m16n8k8.row.col.f32.tf32.tf32.f32 "
        "{%0,%1,%2,%3}, {%4,%5,%6,%7}, {%8,%9}, {%0,%1,%2,%3};"
        : "+f"(c[0]), "+f"(c[1]), "+f"(c[2]), "+f"(c[3])
        : "r"(a[0]), "r"(a[1]), "r"(a[2]), "r"(a[3]), "r"(b[0]), "r"(b[1]));
}

// store one 8-deep K slice (converted to tf32) into a [16][pad] tile
#define STS8(ARR, BUFI, V0, V1)                                               \
    ARR[BUFI][lkh+0][lrow]=f2t(V0.x); ARR[BUFI][lkh+1][lrow]=f2t(V0.y);       \
    ARR[BUFI][lkh+2][lrow]=f2t(V0.z); ARR[BUFI][lkh+3][lrow]=f2t(V0.w);       \
    ARR[BUFI][lkh+4][lrow]=f2t(V1.x); ARR[BUFI][lkh+5][lrow]=f2t(V1.y);       \
    ARR[BUFI][lkh+6][lrow]=f2t(V1.z); ARR[BUFI][lkh+7][lrow]=f2t(V1.w);

// warp-tile compute (4m x 4n of m16n8k8): A,B both [16][pad] k-major tiles
#define COMPUTE_TILE(ASRC, BSRC)                                              \
    _Pragma("unroll")                                                         \
    for (int ks = 0; ks < 16; ks += 8) {                                      \
        unsigned afr[4][4], bfr[4][2];                                        \
        _Pragma("unroll")                                                     \
        for (int mt = 0; mt < 4; mt++) {                                      \
            const int m0 = wm + mt*16 + ar;                                   \
            afr[mt][0] = ASRC[ks+ak][m0];                                     \
            afr[mt][1] = ASRC[ks+ak][m0+8];                                   \
            afr[mt][2] = ASRC[ks+4+ak][m0];                                   \
            afr[mt][3] = ASRC[ks+4+ak][m0+8];                                 \
        }                                                                     \
        _Pragma("unroll")                                                     \
        for (int nt = 0; nt < 4; nt++) {                                      \
            const int n0 = wn + nt*8 + ar;                                    \
            bfr[nt][0] = BSRC[ks+ak][n0];                                     \
            bfr[nt][1] = BSRC[ks+4+ak][n0];                                   \
        }                                                                     \
        _Pragma("unroll")                                                     \
        for (int mt = 0; mt < 4; mt++)                                        \
            _Pragma("unroll")                                                 \
            for (int nt = 0; nt < 4; nt++)                                    \
                mma8(acc[mt][nt], afr[mt], bfr[nt]);                          \
    }

// ============ 128M x 256N TF32 GEMM core (dynamic smem, dbuf) ============
// As: [2][16][136], Bs: [2][16][264]. 8 warps, warp tile 64x64.
constexpr int APAD = 136, BPAD = 264;
constexpr int SMEMDYN = (2 * 16 * APAD + 2 * 16 * BPAD) * 4;

#define GEMM256_PROLOG_AND_LOOP(...)                                          \
    extern __shared__ unsigned smraw[];                                       \
    unsigned (*As)[16][APAD] = (unsigned(*)[16][APAD])smraw;                  \
    unsigned (*Bs)[16][BPAD] = (unsigned(*)[16][BPAD])(smraw + 2*16*APAD);    \
    const int tid = threadIdx.x, lane = tid & 31, w = tid >> 5;               \
    const int bm = blockIdx.y * 128, bn = blockIdx.x * 256;                   \
    const int wm = (w >> 2) * 64, wn = (w & 3) * 64;                          \
    const int lrow = tid & 127, lkh = (tid >> 7) * 8;                         \
    const int ar = lane >> 2, ak = lane & 3;                                  \
    const float* Ap  = A  + (size_t)(bm + lrow) * K + lkh;                    \
    const float* Bp0 = Bm + (size_t)(bn + lrow) * K + lkh;                    \
    const float* Bp1 = Bm + (size_t)(bn + lrow + 128) * K + lkh;              \
    float acc[4][8][4];                                                       \
    _Pragma("unroll")                                                         \
    for (int mt = 0; mt < 4; mt++)                                            \
        _Pragma("unroll")                                                     \
        for (int nt = 0; nt < 8; nt++)                                        \
            _Pragma("unroll")                                                 \
            for (int i = 0; i < 4; i++) acc[mt][nt][i] = 0.f;                 \
    float4 pa0 = *(const float4*)Ap,  pa1 = *(const float4*)(Ap + 4);         \
    float4 pb0 = *(const float4*)Bp0, pb1 = *(const float4*)(Bp0 + 4);        \
    float4 pc0 = *(const float4*)Bp1, pc1 = *(const float4*)(Bp1 + 4);        \
    {                                                                         \
        STS8(As, 0, pa0, pa1);                                                \
        STS8(Bs, 0, pb0, pb1);                                                \
        Bs[0][lkh+0][lrow+128]=f2t(pc0.x); Bs[0][lkh+1][lrow+128]=f2t(pc0.y); \
        Bs[0][lkh+2][lrow+128]=f2t(pc0.z); Bs[0][lkh+3][lrow+128]=f2t(pc0.w); \
        Bs[0][lkh+4][lrow+128]=f2t(pc1.x); Bs[0][lkh+5][lrow+128]=f2t(pc1.y); \
        Bs[0][lkh+6][lrow+128]=f2t(pc1.z); Bs[0][lkh+7][lrow+128]=f2t(pc1.w); \
    }                                                                         \
    __syncthreads();                                                          \
    int buf = 0;                                                              \
    for (int k0 = 0; k0 < K; k0 += 16) {                                      \
        const bool more = (k0 + 16 < K);                                      \
        if (more) {                                                           \
            pa0 = *(const float4*)(Ap  + k0 + 16); pa1 = *(const float4*)(Ap  + k0 + 20); \
            pb0 = *(const float4*)(Bp0 + k0 + 16); pb1 = *(const float4*)(Bp0 + k0 + 20); \
            pc0 = *(const float4*)(Bp1 + k0 + 16); pc1 = *(const float4*)(Bp1 + k0 + 20); \
        }                                                                     \
        _Pragma("unroll")                                                     \
        for (int ks = 0; ks < 16; ks += 8) {                                  \
            unsigned afr[4][4], bfr[8][2];                                    \
            _Pragma("unroll")                                                 \
            for (int mt = 0; mt < 4; mt++) {                                  \
                const int m0 = wm + mt*16 + ar;                               \
                afr[mt][0] = As[buf][ks+ak][m0];                              \
                afr[mt][1] = As[buf][ks+ak][m0+8];                            \
                afr[mt][2] = As[buf][ks+4+ak][m0];                            \
                afr[mt][3] = As[buf][ks+4+ak][m0+8];                          \
            }                                                                 \
            _Pragma("unroll")                                                 \
            for (int nt = 0; nt < 8; nt++) {                                  \
                const int n0 = wn + nt*8 + ar;                                \
                bfr[nt][0] = Bs[buf][ks+ak][n0];                              \
                bfr[nt][1] = Bs[buf][ks+4+ak][n0];                            \
            }                                                                 \
            _Pragma("unroll")                                                 \
            for (int mt = 0; mt < 4; mt++)                                    \
                _Pragma("unroll")                                             \
                for (int nt = 0; nt < 8; nt++)                                \
                    mma8(acc[mt][nt], afr[mt], bfr[nt]);                      \
        }                                                                     \
        if (more) {                                                           \
            const int nb = buf ^ 1;                                           \
            STS8(As, nb, pa0, pa1);                                           \
            STS8(Bs, nb, pb0, pb1);                                           \
            Bs[nb][lkh+0][lrow+128]=f2t(pc0.x); Bs[nb][lkh+1][lrow+128]=f2t(pc0.y); \
            Bs[nb][lkh+2][lrow+128]=f2t(pc0.z); Bs[nb][lkh+3][lrow+128]=f2t(pc0.w); \
            Bs[nb][lkh+4][lrow+128]=f2t(pc1.x); Bs[nb][lkh+5][lrow+128]=f2t(pc1.y); \
            Bs[nb][lkh+6][lrow+128]=f2t(pc1.z); Bs[nb][lkh+7][lrow+128]=f2t(pc1.w); \
        }                                                                     \
        __syncthreads();                                                      \
        buf ^= 1;                                                             \
    }                                                                         \
    __VA_ARGS__

// ====== QKV GEMM (128x256) + in-place fused bias/RoPE + per-head scatter ====
__global__ __launch_bounds__(256) void qkv_gemm_tc(
    const float* __restrict__ A, const float* __restrict__ Bm,
    const float* __restrict__ bias, const int* __restrict__ pos,
    float* __restrict__ qb, float* __restrict__ kb, float* __restrict__ vb)
{
    constexpr int K = HIDc;
    GEMM256_PROLOG_AND_LOOP(
    {
        const int ac2 = (lane & 3) * 2;
        const int cb = bn + wn;                 // 64-aligned chunk base
        const int h = cb / 384;
        const int rm = cb - h * 384;            // 0,64,...,320
        const int sel = rm >> 7;                // 0=q,1=k,2=v (const per chunk)
        const int dbase = rm & 127;             // 0 or 64
        float* basep = (sel == 0) ? qb : (sel == 1) ? kb : vb;
        const bool dorope = (sel < 2) && (dbase == 0);

        _Pragma("unroll")
        for (int mt = 0; mt < 4; mt++) {
            const int r0 = bm + wm + mt * 16 + ar;
            const int bb = r0 >> 11;
            const int s  = r0 & 2047;

            // bias in place (no extra arrays -> no spill pressure)
            _Pragma("unroll")
            for (int nt = 0; nt < 8; nt++) {
                const float b0 = bias[cb + nt * 8 + ac2];
                const float b1 = bias[cb + nt * 8 + ac2 + 1];
                acc[mt][nt][0] += b0; acc[mt][nt][1] += b1;
                acc[mt][nt][2] += b0; acc[mt][nt][3] += b1;
            }

            if (dorope) {
                const float t0 = (float)pos[bb * Sc + s];
                const float t8 = (float)pos[bb * Sc + s + 8];
                _Pragma("unroll")
                for (int nt = 0; nt < 2; nt++) {
                    _Pragma("unroll")
                    for (int i = 0; i < 4; i++) {
                        const int d = nt * 8 + ac2 + (i & 1);   // < 16
                        const float invf =
                            exp2f(-((float)d * (1.0f / 16.0f)) * 13.28771237954945f);
                        const float t = (i >> 1) ? t8 : t0;
                        float sn, cs;
                        sincosf(t * invf, &sn, &cs);
                        const float Av = acc[mt][nt][i];
                        const float Bv = acc[mt][nt + 2][i];
                        acc[mt][nt][i]     = Av * cs - Bv * sn;
                        acc[mt][nt + 2][i] = Bv * cs + Av * sn;
                    }
                }
            }

            _Pragma("unroll")
            for (int nt = 0; nt < 8; nt++) {
                const int d0 = dbase + nt * 8 + ac2;
                float* dst = basep + (((size_t)(bb * NHc + h) * Sc + s) * HDc + d0);
                *(float2*)dst = make_float2(acc[mt][nt][0], acc[mt][nt][1]);
                *(float2*)(dst + (size_t)8 * HDc) =
                    make_float2(acc[mt][nt][2], acc[mt][nt][3]);
            }
        }
    })
}

// ================= dense GEMM (128x256), plain output =======================
__global__ __launch_bounds__(256) void gemm_tn_tc256(
    const float* __restrict__ A, const float* __restrict__ Bm,
    const float* __restrict__ bias, float* __restrict__ C,
    int M, int N, int K)
{
    GEMM256_PROLOG_AND_LOOP(
    {
        const int ac2 = (lane & 3) * 2;
        _Pragma("unroll")
        for (int nt = 0; nt < 8; nt++) {
            const int col = bn + wn + nt * 8 + ac2;
            const float b0 = bias[col];
            const float b1 = bias[col + 1];
            _Pragma("unroll")
            for (int mt = 0; mt < 4; mt++) {
                const int r0 = bm + wm + mt * 16 + ar;
                *(float2*)&C[(size_t)r0 * N + col] =
                    make_float2(acc[mt][nt][0] + b0, acc[mt][nt][1] + b1);
                *(float2*)&C[(size_t)(r0 + 8) * N + col] =
                    make_float2(acc[mt][nt][2] + b0, acc[mt][nt][3] + b1);
            }
        }
    })
}

// ================= scores = scale * Q K^T (TF32, causal tiles, dbuf) =========
__global__ __launch_bounds__(256) void scores_tc()
{
    if (blockIdx.x > blockIdx.y) return;
    constexpr float SCALE = 0.08838834764831845f;  // 1/sqrt(128)
    __shared__ unsigned As[2][16][APAD];
    __shared__ unsigned Bs[2][16][APAD];

    const int tid = threadIdx.x, lane = tid & 31, w = tid >> 5;
    const int bh = blockIdx.z;
    const int bm = blockIdx.y * 128, bn = blockIdx.x * 128;
    const int wm = (w >> 2) * 64, wn = (w & 3) * 32;
    const int lrow = tid & 127, lkh = (tid >> 7) * 8;
    const int ar = lane >> 2, ak = lane & 3;

    const float* Ap = g_q + (size_t)bh * Sc * HDc + (size_t)(bm + lrow) * HDc + lkh;
    const float* Bp = g_k + (size_t)bh * Sc * HDc + (size_t)(bn + lrow) * HDc + lkh;
    float* C = g_attn + (size_t)bh * Sc * Sc;

    float acc[4][4][4];
#pragma unroll
    for (int mt = 0; mt < 4; mt++)
#pragma unroll
        for (int nt = 0; nt < 4; nt++)
#pragma unroll
            for (int i = 0; i < 4; i++) acc[mt][nt][i] = 0.f;

    float4 pa0 = *(const float4*)Ap, pa1 = *(const float4*)(Ap + 4);
    float4 pb0 = *(const float4*)Bp, pb1 = *(const float4*)(Bp + 4);
    STS8(As, 0, pa0, pa1);
    STS8(Bs, 0, pb0, pb1);
    __syncthreads();

    int buf = 0;
    for (int k0 = 0; k0 < HDc; k0 += 16) {
        const bool more = (k0 + 16 < HDc);
        if (more) {
            pa0 = *(const float4*)(Ap + k0 + 16); pa1 = *(const float4*)(Ap + k0 + 20);
            pb0 = *(const float4*)(Bp + k0 + 16); pb1 = *(const float4*)(Bp + k0 + 20);
        }
        COMPUTE_TILE(As[buf], Bs[buf]);
        if (more) {
            const int nb = buf ^ 1;
            STS8(As, nb, pa0, pa1);
            STS8(Bs, nb, pb0, pb1);
        }
        __syncthreads();
        buf ^= 1;
    }

    const int ac2 = (lane & 3) * 2;
#pragma unroll
    for (int nt = 0; nt < 4; nt++) {
        const int col = bn + wn + nt * 8 + ac2;
#pragma unroll
        for (int mt = 0; mt < 4; mt++) {
            const int r0 = bm + wm + mt * 16 + ar;
            *(float2*)&C[(size_t)r0 * Sc + col] =
                make_float2(acc[mt][nt][0] * SCALE, acc[mt][nt][1] * SCALE);
            *(float2*)&C[(size_t)(r0 + 8) * Sc + col] =
                make_float2(acc[mt][nt][2] * SCALE, acc[mt][nt][3] * SCALE);
        }
    }
}

// ---------------- causal row softmax, float4 over valid groups ----------------
__global__ __launch_bounds__(256) void softmax_kernel(const float* __restrict__ amask)
{
    const int row = blockIdx.x;
    const int q = row & (Sc - 1);
    const int b = row >> 15;               // / (NHc*Sc)
    float* ap = g_attn + (size_t)row * Sc;
    const float* mp = amask + (size_t)b * Sc;

    const int tid = threadIdx.x, lane = tid & 31, w = tid >> 5;
    __shared__ float sred[8];

    const int nv = (q >> 2) + 1;           // float4 groups covering [0, q]
    float4 x[2];
    float lm = -3.4e38f;
#pragma unroll
    for (int it = 0; it < 2; it++) {
        const int g = tid + it * 256;
        if (g < nv) {
            float4 v = *(const float4*)(ap + g * 4);
            float4 m = *(const float4*)(mp + g * 4);
            const int k = g * 4;
            v.x = (k + 0 <= q) ? v.x + m.x : -3.4e38f;
            v.y = (k + 1 <= q) ? v.y + m.y : -3.4e38f;
            v.z = (k + 2 <= q) ? v.z + m.z : -3.4e38f;
            v.w = (k + 3 <= q) ? v.w + m.w : -3.4e38f;
            x[it] = v;
            lm = fmaxf(lm, fmaxf(fmaxf(v.x, v.y), fmaxf(v.z, v.w)));
        } else {
            x[it] = make_float4(-3.4e38f, -3.4e38f, -3.4e38f, -3.4e38f);
        }
    }
#pragma unroll
    for (int o = 16; o > 0; o >>= 1) lm = fmaxf(lm, __shfl_xor_sync(0xffffffffu, lm, o));
    if (lane == 0) sred[w] = lm;
    __syncthreads();
    float m = sred[0];
#pragma unroll
    for (int i = 1; i < 8; i++) m = fmaxf(m, sred[i]);
    __syncthreads();

    float ls = 0.f;
#pragma unroll
    for (int it = 0; it < 2; it++) {
        const int g = tid + it * 256;
        if (g < nv) {
            float4 v = x[it];
            v.x = __expf(v.x - m); v.y = __expf(v.y - m);
            v.z = __expf(v.z - m); v.w = __expf(v.w - m);
            x[it] = v;
            ls += v.x + v.y + v.z + v.w;
        }
    }
#pragma unroll
    for (int o = 16; o > 0; o >>= 1) ls += __shfl_xor_sync(0xffffffffu, ls, o);
    if (lane == 0) sred[w] = ls;
    __syncthreads();
    float s = 0.f;
#pragma unroll
    for (int i = 0; i < 8; i++) s += sred[i];
    const float inv = 1.0f / s;

#pragma unroll
    for (int it = 0; it < 2; it++) {
        const int g = tid + it * 256;
        if (g < nv) {
            float4 v = x[it];
            *(float4*)(ap + g * 4) =
                make_float4(v.x * inv, v.y * inv, v.z * inv, v.w * inv);
        }
    }
}

// ---------------- column-sum partials per q-chunk (deterministic) ----------------
__global__ void colpart_kernel()
{
    const int k = blockIdx.x * 256 + threadIdx.x;
    const int h = blockIdx.y;
    const int z = blockIdx.z;
    const int qlo = z * 256, qhi = qlo + 256;
    const int qs = (k > qlo) ? k : qlo;
    const bool rz = (z == NQCH - 1);
    float s = 0.f, r = 0.f;
    for (int b = 0; b < Bc; b++) {
        const float* ap = g_attn + ((size_t)(b * NHc + h)) * Sc * Sc;
        for (int q = qs; q < qhi; q++) {
            float a = ap[(size_t)q * Sc + k];
            s += a;
            if (rz && q >= Sc - MBc) r += a;
        }
    }
    g_colpart[((size_t)z * NHc + h) * Sc + k] = s;
    if (rz) g_ratio[h * Sc + k] = r;
}

__global__ void colsumfin_kernel()
{
    const int k = blockIdx.x * 256 + threadIdx.x;
    const int h = blockIdx.y;
    float s = 0.f;
#pragma unroll
    for (int z = 0; z < NQCH; z++) s += g_colpart[((size_t)z * NHc + h) * Sc + k];
    g_colsum[h * Sc + k] = s;
}

// ---------------- top-k per head (jax tie-break: lowest index) ----------------
__global__ __launch_bounds__(256) void topk_kernel()
{
    const int h = blockIdx.x, tid = threadIdx.x;
    __shared__ float tv[NCAND];
    __shared__ float rv[256];
    __shared__ int   ri[256];

    for (int i = tid; i < NCAND; i += 256) tv[i] = g_colsum[h * Sc + SBc + i];
    __syncthreads();

    for (int r = 0; r < TKc; r++) {
        float bv = -1e30f; int bi = NCAND;
        for (int i = tid; i < NCAND; i += 256) {
            float v = tv[i];
            if (v > bv) { bv = v; bi = i; }
        }
        rv[tid] = bv; ri[tid] = bi;
        __syncthreads();
        for (int st = 128; st > 0; st >>= 1) {
            if (tid < st) {
                if (rv[tid + st] > rv[tid] ||
                    (rv[tid + st] == rv[tid] && ri[tid + st] < ri[tid])) {
                    rv[tid] = rv[tid + st]; ri[tid] = ri[tid + st];
                }
            }
            __syncthreads();
        }
        if (tid == 0) {
            const int gi = ri[0] + SBc;
            g_topidx[h * TKc + r] = gi;
            g_topval[h * TKc + r] = g_ratio[h * Sc + gi] * (1.0f / MBc);
            tv[ri[0]] = -1e30f;
        }
        __syncthreads();
    }
}

// ---------------- v[b,h,SB,:] = sum_j v[b,h,idx_j,:] * val_j ----------------
__global__ void vupdate_kernel()
{
    const int bh = blockIdx.x;
    const int h  = bh % NHc;
    const int d  = threadIdx.x;
    float* vp = g_v + (size_t)bh * Sc * HDc;
    float acc = 0.f;
#pragma unroll
    for (int j = 0; j < TKc; j++)
        acc += vp[(size_t)g_topidx[h * TKc + j] * HDc + d] * g_topval[h * TKc + j];
    vp[(size_t)SBc * HDc + d] = acc;
}

// ================= out = attn @ v (TF32, causal, dbuf), scatter ==============
__global__ __launch_bounds__(256) void attnv_tc()
{
    __shared__ unsigned As[2][16][APAD]; // [k][m]
    __shared__ unsigned Vs[2][128][20];  // [n][k]

    const int tid = threadIdx.x, lane = tid & 31, w = tid >> 5;
    const int bh = blockIdx.y;
    const int bm = blockIdx.x * 128;
    const int wm = (w >> 2) * 64, wn = (w & 3) * 32;
    const int ar = lane >> 2, ak = lane & 3;

    const float* attn = g_attn + (size_t)bh * Sc * Sc;
    const float* vp   = g_v    + (size_t)bh * Sc * HDc;

    const int lrow = tid & 127, lkh = (tid >> 7) * 8;
    const int q_l = bm + lrow;
    const float* arow = attn + (size_t)q_l * Sc;
    const int vk = tid & 15, vn = (tid >> 4) * 8;

    float acc[4][4][4];
#pragma unroll
    for (int mt = 0; mt < 4; mt++)
#pragma unroll
        for (int nt = 0; nt < 4; nt++)
#pragma unroll
            for (int i = 0; i < 4; i++) acc[mt][nt][i] = 0.f;

    const int kend = bm + 128;

#define STS_A_MASKED(BUFI, V0, V1, KB)                                        \
    As[BUFI][lkh+0][lrow] = ((KB)+0 <= q_l) ? f2t(V0.x) : 0u;                 \
    As[BUFI][lkh+1][lrow] = ((KB)+1 <= q_l) ? f2t(V0.y) : 0u;                 \
    As[BUFI][lkh+2][lrow] = ((KB)+2 <= q_l) ? f2t(V0.z) : 0u;                 \
    As[BUFI][lkh+3][lrow] = ((KB)+3 <= q_l) ? f2t(V0.w) : 0u;                 \
    As[BUFI][lkh+4][lrow] = ((KB)+4 <= q_l) ? f2t(V1.x) : 0u;                 \
    As[BUFI][lkh+5][lrow] = ((KB)+5 <= q_l) ? f2t(V1.y) : 0u;                 \
    As[BUFI][lkh+6][lrow] = ((KB)+6 <= q_l) ? f2t(V1.z) : 0u;                 \
    As[BUFI][lkh+7][lrow] = ((KB)+7 <= q_l) ? f2t(V1.w) : 0u;

#define STS_V(BUFI, V0, V1)                                                   \
    Vs[BUFI][vn+0][vk]=f2t(V0.x); Vs[BUFI][vn+1][vk]=f2t(V0.y);               \
    Vs[BUFI][vn+2][vk]=f2t(V0.z); Vs[BUFI][vn+3][vk]=f2t(V0.w);               \
    Vs[BUFI][vn+4][vk]=f2t(V1.x); Vs[BUFI][vn+5][vk]=f2t(V1.y);               \
    Vs[BUFI][vn+6][vk]=f2t(V1.z); Vs[BUFI][vn+7][vk]=f2t(V1.w);

    // prologue: tile k0 = 0
    {
        float4 a0v = *(const float4*)(arow + lkh);
        float4 a1v = *(const float4*)(arow + lkh + 4);
        STS_A_MASKED(0, a0v, a1v, lkh);
        const float* vr = vp + (size_t)vk * HDc + vn;
        float4 v0 = *(const float4*)vr, v1 = *(const float4*)(vr + 4);
        STS_V(0, v0, v1);
    }
    __syncthreads();

    int buf = 0;
    for (int k0 = 0; k0 < kend; k0 += 16) {
        const bool more = (k0 + 16 < kend);
        float4 a0v, a1v, v0, v1;
        if (more) {
            a0v = *(const float4*)(arow + k0 + 16 + lkh);
            a1v = *(const float4*)(arow + k0 + 20 + lkh);
            const float* vr = vp + (size_t)(k0 + 16 + vk) * HDc + vn;
            v0 = *(const float4*)vr; v1 = *(const float4*)(vr + 4);
        }

#pragma unroll
        for (int ks = 0; ks < 16; ks += 8) {
            unsigned afr[4][4], bfr[4][2];
#pragma unroll
            for (int mt = 0; mt < 4; mt++) {
                const int m0 = wm + mt * 16 + ar;
                afr[mt][0] = As[buf][ks+ak][m0];
                afr[mt][1] = As[buf][ks+ak][m0+8];
                afr[mt][2] = As[buf][ks+4+ak][m0];
                afr[mt][3] = As[buf][ks+4+ak][m0+8];
            }
#pragma unroll
            for (int nt = 0; nt < 4; nt++) {
                const int n0 = wn + nt * 8 + ar;
                bfr[nt][0] = Vs[buf][n0][ks+ak];
                bfr[nt][1] = Vs[buf][n0][ks+4+ak];
            }
#pragma unroll
            for (int mt = 0; mt < 4; mt++)
#pragma unroll
                for (int nt = 0; nt < 4; nt++) mma8(acc[mt][nt], afr[mt], bfr[nt]);
        }

        if (more) {
            const int nb = buf ^ 1;
            const int kb2 = k0 + 16 + lkh;
            STS_A_MASKED(nb, a0v, a1v, kb2);
            STS_V(nb, v0, v1);
        }
        __syncthreads();
        buf ^= 1;
    }

    const int b = bh >> 4, h = bh & 15;
    const int ac2 = (lane & 3) * 2;
#pragma unroll
    for (int nt = 0; nt < 4; nt++) {
        const int col = h * HDc + wn + nt * 8 + ac2;
#pragma unroll
        for (int mt = 0; mt < 4; mt++) {
            const int q = bm + wm + mt * 16 + ar;
            *(float2*)&g_outh[((size_t)(b * Sc + q)) * HIDc + col] =
                make_float2(acc[mt][nt][0], acc[mt][nt][1]);
            *(float2*)&g_outh[((size_t)(b * Sc + q + 8)) * HIDc + col] =
                make_float2(acc[mt][nt][2], acc[mt][nt][3]);
        }
    }
#undef STS_A_MASKED
#undef STS_V
}

// ---------------- launch ----------------
extern "C" void kernel_launch(void* const* d_in, const int* in_sizes, int n_in,
                              void* d_out, int out_size)
{
    (void)in_sizes; (void)n_in; (void)out_size;
    const float* hs    = (const float*)d_in[0];
    const float* amask = (const float*)d_in[1];
    const int*   pos   = (const int*)  d_in[2];
    const float* Wqkv  = (const float*)d_in[3];
    const float* bqkv  = (const float*)d_in[4];
    const float* Wd    = (const float*)d_in[5];
    const float* bd    = (const float*)d_in[6];
    float* out = (float*)d_out;

    void *p_q = nullptr, *p_k = nullptr, *p_v = nullptr, *p_outh = nullptr;
    cudaGetSymbolAddress(&p_q, g_q);
    cudaGetSymbolAddress(&p_k, g_k);
    cudaGetSymbolAddress(&p_v, g_v);
    cudaGetSymbolAddress(&p_outh, g_outh);

    cudaFuncSetAttribute(qkv_gemm_tc,
                         cudaFuncAttributeMaxDynamicSharedMemorySize, SMEMDYN);
    cudaFuncSetAttribute(gemm_tn_tc256,
                         cudaFuncAttributeMaxDynamicSharedMemorySize, SMEMDYN);

    // 1. QKV projection + in-place fused bias/RoPE + per-head scatter
    qkv_gemm_tc<<<dim3(3 * HIDc / 256, (Bc * Sc) / 128), 256, SMEMDYN>>>(
        hs, Wqkv, bqkv, pos, (float*)p_q, (float*)p_k, (float*)p_v);

    // 2. scaled QK^T (causal tiles, TF32, dbuf)
    scores_tc<<<dim3(Sc / 128, Sc / 128, Bc * NHc), 256>>>();

    // 3. row softmax (vectorized, causal groups only)
    softmax_kernel<<<Bc * NHc * Sc, 256>>>(amask);

    // 4a/4b. column statistics: per-chunk partials + fixed-order sum
    colpart_kernel<<<dim3(Sc / 256, NHc, NQCH), 256>>>();
    colsumfin_kernel<<<dim3(Sc / 256, NHc), 256>>>();

    // 5. per-head top-16
    topk_kernel<<<NHc, 256>>>();

    // 6. merged row write into v
    vupdate_kernel<<<Bc * NHc, HDc>>>();

    // 7. attn @ v (TF32, dbuf)
    attnv_tc<<<dim3(Sc / 128, Bc * NHc), 256>>>();

    // 8. dense projection (TF32, 128x256)
    gemm_tn_tc256<<<dim3(HIDc / 256, (Bc * Sc) / 128), 256, SMEMDYN>>>(
        (const float*)p_outh, Wd, bd, out, Bc * Sc, HIDc, HIDc);
}

// round 17
// speedup vs baseline: 1.5239x; 1.5210x over previous
#include <cuda_runtime.h>
#include <math.h>

// ---------------- problem constants ----------------
constexpr int Bc   = 2;
constexpr int Sc   = 2048;
constexpr int HIDc = 2048;
constexpr int NHc  = 16;
constexpr int HDc  = 128;
constexpr int RDc  = 32;
constexpr int SBc  = 204;           // int(0.1 * S)
constexpr int RBc  = 204;           // int(0.1 * S)
constexpr int MBc  = 128;           // MERGE_BUDGET
constexpr int TKc  = 16;            // TOPK
constexpr int NCAND = Sc - RBc - SBc;   // 1640 candidates
constexpr int NQCH = 16;            // colreduce q-chunks (128 rows each)

// ---------------- device scratch (static, allocation-free) ----------------
__device__ float g_q   [(size_t)Bc * NHc * Sc * HDc];    //  32 MB
__device__ float g_k   [(size_t)Bc * NHc * Sc * HDc];    //  32 MB
__device__ float g_v   [(size_t)Bc * NHc * Sc * HDc];    //  32 MB
__device__ float g_attn[(size_t)Bc * NHc * Sc * Sc];     // 512 MB
__device__ float g_outh[(size_t)Bc * Sc * HIDc];         //  32 MB
__device__ float g_colpart[(size_t)NQCH * NHc * Sc];
__device__ float g_colsum[NHc * Sc];
__device__ float g_ratio [NHc * Sc];
__device__ int   g_topidx[NHc * TKc];
__device__ float g_topval[NHc * TKc];

// ---------------- tf32 helpers ----------------
__device__ __forceinline__ unsigned f2t(float x) {
    unsigned r; asm("cvt.rna.tf32.f32 %0, %1;" : "=r"(r) : "f"(x)); return r;
}
__device__ __forceinline__ void mma8(float* c, const unsigned* a, const unsigned* b) {
    asm volatile(
        "mma.sync.aligned.m16n8k8.row.col.f32.tf32.tf32.f32 "
        "{%0,%1,%2,%3}, {%4,%5,%6,%7}, {%8,%9}, {%0,%1,%2,%3};"
        : "+f"(c[0]), "+f"(c[1]), "+f"(c[2]), "+f"(c[3])
        : "r"(a[0]), "r"(a[1]), "r"(a[2]), "r"(a[3]), "r"(b[0]), "r"(b[1]));
}

// store one 8-deep K slice (converted to tf32) into a [16][pad] tile
#define STS8(ARR, BUFI, V0, V1)                                               \
    ARR[BUFI][lkh+0][lrow]=f2t(V0.x); ARR[BUFI][lkh+1][lrow]=f2t(V0.y);       \
    ARR[BUFI][lkh+2][lrow]=f2t(V0.z); ARR[BUFI][lkh+3][lrow]=f2t(V0.w);       \
    ARR[BUFI][lkh+4][lrow]=f2t(V1.x); ARR[BUFI][lkh+5][lrow]=f2t(V1.y);       \
    ARR[BUFI][lkh+6][lrow]=f2t(V1.z); ARR[BUFI][lkh+7][lrow]=f2t(V1.w);

// warp-tile compute (4m x 4n of m16n8k8): A,B both [16][pad] k-major tiles
#define COMPUTE_TILE(ASRC, BSRC)                                              \
    _Pragma("unroll")                                                         \
    for (int ks = 0; ks < 16; ks += 8) {                                      \
        unsigned afr[4][4], bfr[4][2];                                        \
        _Pragma("unroll")                                                     \
        for (int mt = 0; mt < 4; mt++) {                                      \
            const int m0 = wm + mt*16 + ar;                                   \
            afr[mt][0] = ASRC[ks+ak][m0];                                     \
            afr[mt][1] = ASRC[ks+ak][m0+8];                                   \
            afr[mt][2] = ASRC[ks+4+ak][m0];                                   \
            afr[mt][3] = ASRC[ks+4+ak][m0+8];                                 \
        }                                                                     \
        _Pragma("unroll")                                                     \
        for (int nt = 0; nt < 4; nt++) {                                      \
            const int n0 = wn + nt*8 + ar;                                    \
            bfr[nt][0] = BSRC[ks+ak][n0];                                     \
            bfr[nt][1] = BSRC[ks+4+ak][n0];                                   \
        }                                                                     \
        _Pragma("unroll")                                                     \
        for (int mt = 0; mt < 4; mt++)                                        \
            _Pragma("unroll")                                                 \
            for (int nt = 0; nt < 4; nt++)                                    \
                mma8(acc[mt][nt], afr[mt], bfr[nt]);                          \
    }

// ============ 128M x 256N TF32 GEMM core (dynamic smem, dbuf) ============
// As: [2][16][136], Bs: [2][16][264]. 8 warps, warp tile 64x64.
// NOTE: variadic so the epilogue block may contain brace-level commas.
constexpr int APAD = 136, BPAD = 264;
constexpr int SMEMDYN = (2 * 16 * APAD + 2 * 16 * BPAD) * 4;

#define GEMM256_PROLOG_AND_LOOP(...)                                          \
    extern __shared__ unsigned smraw[];                                       \
    unsigned (*As)[16][APAD] = (unsigned(*)[16][APAD])smraw;                  \
    unsigned (*Bs)[16][BPAD] = (unsigned(*)[16][BPAD])(smraw + 2*16*APAD);    \
    const int tid = threadIdx.x, lane = tid & 31, w = tid >> 5;               \
    const int bm = blockIdx.y * 128, bn = blockIdx.x * 256;                   \
    const int wm = (w >> 2) * 64, wn = (w & 3) * 64;                          \
    const int lrow = tid & 127, lkh = (tid >> 7) * 8;                         \
    const int ar = lane >> 2, ak = lane & 3;                                  \
    const float* Ap  = A  + (size_t)(bm + lrow) * K + lkh;                    \
    const float* Bp0 = Bm + (size_t)(bn + lrow) * K + lkh;                    \
    const float* Bp1 = Bm + (size_t)(bn + lrow + 128) * K + lkh;              \
    float acc[4][8][4];                                                       \
    _Pragma("unroll")                                                         \
    for (int mt = 0; mt < 4; mt++)                                            \
        _Pragma("unroll")                                                     \
        for (int nt = 0; nt < 8; nt++)                                        \
            _Pragma("unroll")                                                 \
            for (int i = 0; i < 4; i++) acc[mt][nt][i] = 0.f;                 \
    float4 pa0 = *(const float4*)Ap,  pa1 = *(const float4*)(Ap + 4);         \
    float4 pb0 = *(const float4*)Bp0, pb1 = *(const float4*)(Bp0 + 4);        \
    float4 pc0 = *(const float4*)Bp1, pc1 = *(const float4*)(Bp1 + 4);        \
    {                                                                         \
        STS8(As, 0, pa0, pa1);                                                \
        STS8(Bs, 0, pb0, pb1);                                                \
        Bs[0][lkh+0][lrow+128]=f2t(pc0.x); Bs[0][lkh+1][lrow+128]=f2t(pc0.y); \
        Bs[0][lkh+2][lrow+128]=f2t(pc0.z); Bs[0][lkh+3][lrow+128]=f2t(pc0.w); \
        Bs[0][lkh+4][lrow+128]=f2t(pc1.x); Bs[0][lkh+5][lrow+128]=f2t(pc1.y); \
        Bs[0][lkh+6][lrow+128]=f2t(pc1.z); Bs[0][lkh+7][lrow+128]=f2t(pc1.w); \
    }                                                                         \
    __syncthreads();                                                          \
    int buf = 0;                                                              \
    for (int k0 = 0; k0 < K; k0 += 16) {                                      \
        const bool more = (k0 + 16 < K);                                      \
        if (more) {                                                           \
            pa0 = *(const float4*)(Ap  + k0 + 16); pa1 = *(const float4*)(Ap  + k0 + 20); \
            pb0 = *(const float4*)(Bp0 + k0 + 16); pb1 = *(const float4*)(Bp0 + k0 + 20); \
            pc0 = *(const float4*)(Bp1 + k0 + 16); pc1 = *(const float4*)(Bp1 + k0 + 20); \
        }                                                                     \
        _Pragma("unroll")                                                     \
        for (int ks = 0; ks < 16; ks += 8) {                                  \
            unsigned afr[4][4], bfr[8][2];                                    \
            _Pragma("unroll")                                                 \
            for (int mt = 0; mt < 4; mt++) {                                  \
                const int m0 = wm + mt*16 + ar;                               \
                afr[mt][0] = As[buf][ks+ak][m0];                              \
                afr[mt][1] = As[buf][ks+ak][m0+8];                            \
                afr[mt][2] = As[buf][ks+4+ak][m0];                            \
                afr[mt][3] = As[buf][ks+4+ak][m0+8];                          \
            }                                                                 \
            _Pragma("unroll")                                                 \
            for (int nt = 0; nt < 8; nt++) {                                  \
                const int n0 = wn + nt*8 + ar;                                \
                bfr[nt][0] = Bs[buf][ks+ak][n0];                              \
                bfr[nt][1] = Bs[buf][ks+4+ak][n0];                            \
            }                                                                 \
            _Pragma("unroll")                                                 \
            for (int mt = 0; mt < 4; mt++)                                    \
                _Pragma("unroll")                                             \
                for (int nt = 0; nt < 8; nt++)                                \
                    mma8(acc[mt][nt], afr[mt], bfr[nt]);                      \
        }                                                                     \
        if (more) {                                                           \
            const int nb = buf ^ 1;                                           \
            STS8(As, nb, pa0, pa1);                                           \
            STS8(Bs, nb, pb0, pb1);                                           \
            Bs[nb][lkh+0][lrow+128]=f2t(pc0.x); Bs[nb][lkh+1][lrow+128]=f2t(pc0.y); \
            Bs[nb][lkh+2][lrow+128]=f2t(pc0.z); Bs[nb][lkh+3][lrow+128]=f2t(pc0.w); \
            Bs[nb][lkh+4][lrow+128]=f2t(pc1.x); Bs[nb][lkh+5][lrow+128]=f2t(pc1.y); \
            Bs[nb][lkh+6][lrow+128]=f2t(pc1.z); Bs[nb][lkh+7][lrow+128]=f2t(pc1.w); \
        }                                                                     \
        __syncthreads();                                                      \
        buf ^= 1;                                                             \
    }                                                                         \
    __VA_ARGS__

// ================= QKV GEMM (128x256) with per-head scatter epilogue ========
__global__ __launch_bounds__(256) void qkv_gemm_tc(
    const float* __restrict__ A, const float* __restrict__ Bm,
    const float* __restrict__ bias,
    float* __restrict__ qb, float* __restrict__ kb, float* __restrict__ vb)
{
    constexpr int K = HIDc;
    GEMM256_PROLOG_AND_LOOP(
    {
        const int ac2 = (lane & 3) * 2;
        _Pragma("unroll")
        for (int nt = 0; nt < 8; nt++) {
            const int col = bn + wn + nt * 8 + ac2;
            const int h = col / 384;
            const int r = col - h * 384;
            float* basep = (r < 128) ? qb : (r < 256) ? kb : vb;
            const int d = r & 127;
            const float b0 = bias[col];
            const float b1 = bias[col + 1];
            _Pragma("unroll")
            for (int mt = 0; mt < 4; mt++) {
                const int r0 = bm + wm + mt * 16 + ar;
                const int bb = r0 >> 11;
                const int s = r0 & 2047;
                float* dst = basep + (((size_t)(bb * NHc + h) * Sc + s) * HDc + d);
                *(float2*)dst = make_float2(acc[mt][nt][0] + b0, acc[mt][nt][1] + b1);
                *(float2*)(dst + (size_t)8 * HDc) =
                    make_float2(acc[mt][nt][2] + b0, acc[mt][nt][3] + b1);
            }
        }
    })
}

// ================= dense GEMM (128x256), plain output =======================
__global__ __launch_bounds__(256) void gemm_tn_tc256(
    const float* __restrict__ A, const float* __restrict__ Bm,
    const float* __restrict__ bias, float* __restrict__ C,
    int M, int N, int K)
{
    GEMM256_PROLOG_AND_LOOP(
    {
        const int ac2 = (lane & 3) * 2;
        _Pragma("unroll")
        for (int nt = 0; nt < 8; nt++) {
            const int col = bn + wn + nt * 8 + ac2;
            const float b0 = bias[col];
            const float b1 = bias[col + 1];
            _Pragma("unroll")
            for (int mt = 0; mt < 4; mt++) {
                const int r0 = bm + wm + mt * 16 + ar;
                *(float2*)&C[(size_t)r0 * N + col] =
                    make_float2(acc[mt][nt][0] + b0, acc[mt][nt][1] + b1);
                *(float2*)&C[(size_t)(r0 + 8) * N + col] =
                    make_float2(acc[mt][nt][2] + b0, acc[mt][nt][3] + b1);
            }
        }
    })
}

// ---------------- RoPE in place on first RD dims of g_q / g_k ----------------
__global__ void rope_inplace(const int* __restrict__ pos)
{
    const int s = blockIdx.x, h = blockIdx.y, b = blockIdx.z;
    const int t = threadIdx.x;                 // 0..63; warp0 = q, warp1 = k
    const int d = t & 31;
    float* base = ((t < 32) ? g_q : g_k) + (((size_t)(b * NHc + h) * Sc + s) * HDc);
    float x = base[d];
    float partner = __shfl_xor_sync(0xffffffffu, x, 16);
    const int i = d & 15;
    const float invf = exp2f(-((float)i * (1.0f / 16.0f)) * 13.28771237954945f);
    const float ang = (float)pos[b * Sc + s] * invf;
    float sn, c;
    sincosf(ang, &sn, &c);
    base[d] = (d < 16) ? (x * c - partner * sn) : (x * c + partner * sn);
}

// ================= scores = scale * Q K^T (TF32, causal tiles, dbuf) =========
__global__ __launch_bounds__(256) void scores_tc()
{
    if (blockIdx.x > blockIdx.y) return;
    constexpr float SCALE = 0.08838834764831845f;  // 1/sqrt(128)
    __shared__ unsigned As[2][16][APAD];
    __shared__ unsigned Bs[2][16][APAD];

    const int tid = threadIdx.x, lane = tid & 31, w = tid >> 5;
    const int bh = blockIdx.z;
    const int bm = blockIdx.y * 128, bn = blockIdx.x * 128;
    const int wm = (w >> 2) * 64, wn = (w & 3) * 32;
    const int lrow = tid & 127, lkh = (tid >> 7) * 8;
    const int ar = lane >> 2, ak = lane & 3;

    const float* Ap = g_q + (size_t)bh * Sc * HDc + (size_t)(bm + lrow) * HDc + lkh;
    const float* Bp = g_k + (size_t)bh * Sc * HDc + (size_t)(bn + lrow) * HDc + lkh;
    float* C = g_attn + (size_t)bh * Sc * Sc;

    float acc[4][4][4];
#pragma unroll
    for (int mt = 0; mt < 4; mt++)
#pragma unroll
        for (int nt = 0; nt < 4; nt++)
#pragma unroll
            for (int i = 0; i < 4; i++) acc[mt][nt][i] = 0.f;

    float4 pa0 = *(const float4*)Ap, pa1 = *(const float4*)(Ap + 4);
    float4 pb0 = *(const float4*)Bp, pb1 = *(const float4*)(Bp + 4);
    STS8(As, 0, pa0, pa1);
    STS8(Bs, 0, pb0, pb1);
    __syncthreads();

    int buf = 0;
    for (int k0 = 0; k0 < HDc; k0 += 16) {
        const bool more = (k0 + 16 < HDc);
        if (more) {
            pa0 = *(const float4*)(Ap + k0 + 16); pa1 = *(const float4*)(Ap + k0 + 20);
            pb0 = *(const float4*)(Bp + k0 + 16); pb1 = *(const float4*)(Bp + k0 + 20);
        }
        COMPUTE_TILE(As[buf], Bs[buf]);
        if (more) {
            const int nb = buf ^ 1;
            STS8(As, nb, pa0, pa1);
            STS8(Bs, nb, pb0, pb1);
        }
        __syncthreads();
        buf ^= 1;
    }

    const int ac2 = (lane & 3) * 2;
#pragma unroll
    for (int nt = 0; nt < 4; nt++) {
        const int col = bn + wn + nt * 8 + ac2;
#pragma unroll
        for (int mt = 0; mt < 4; mt++) {
            const int r0 = bm + wm + mt * 16 + ar;
            *(float2*)&C[(size_t)r0 * Sc + col] =
                make_float2(acc[mt][nt][0] * SCALE, acc[mt][nt][1] * SCALE);
            *(float2*)&C[(size_t)(r0 + 8) * Sc + col] =
                make_float2(acc[mt][nt][2] * SCALE, acc[mt][nt][3] * SCALE);
        }
    }
}

// ---------------- causal row softmax, float4 over valid groups ----------------
__global__ __launch_bounds__(256) void softmax_kernel(const float* __restrict__ amask)
{
    const int row = blockIdx.x;
    const int q = row & (Sc - 1);
    const int b = row >> 15;               // / (NHc*Sc)
    float* ap = g_attn + (size_t)row * Sc;
    const float* mp = amask + (size_t)b * Sc;

    const int tid = threadIdx.x, lane = tid & 31, w = tid >> 5;
    __shared__ float sred[8];

    const int nv = (q >> 2) + 1;           // float4 groups covering [0, q]
    float4 x[2];
    float lm = -3.4e38f;
#pragma unroll
    for (int it = 0; it < 2; it++) {
        const int g = tid + it * 256;
        if (g < nv) {
            float4 v = *(const float4*)(ap + g * 4);
            float4 m = *(const float4*)(mp + g * 4);
            const int k = g * 4;
            v.x = (k + 0 <= q) ? v.x + m.x : -3.4e38f;
            v.y = (k + 1 <= q) ? v.y + m.y : -3.4e38f;
            v.z = (k + 2 <= q) ? v.z + m.z : -3.4e38f;
            v.w = (k + 3 <= q) ? v.w + m.w : -3.4e38f;
            x[it] = v;
            lm = fmaxf(lm, fmaxf(fmaxf(v.x, v.y), fmaxf(v.z, v.w)));
        } else {
            x[it] = make_float4(-3.4e38f, -3.4e38f, -3.4e38f, -3.4e38f);
        }
    }
#pragma unroll
    for (int o = 16; o > 0; o >>= 1) lm = fmaxf(lm, __shfl_xor_sync(0xffffffffu, lm, o));
    if (lane == 0) sred[w] = lm;
    __syncthreads();
    float m = sred[0];
#pragma unroll
    for (int i = 1; i < 8; i++) m = fmaxf(m, sred[i]);
    __syncthreads();

    float ls = 0.f;
#pragma unroll
    for (int it = 0; it < 2; it++) {
        const int g = tid + it * 256;
        if (g < nv) {
            float4 v = x[it];
            v.x = __expf(v.x - m); v.y = __expf(v.y - m);
            v.z = __expf(v.z - m); v.w = __expf(v.w - m);
            x[it] = v;
            ls += v.x + v.y + v.z + v.w;
        }
    }
#pragma unroll
    for (int o = 16; o > 0; o >>= 1) ls += __shfl_xor_sync(0xffffffffu, ls, o);
    if (lane == 0) sred[w] = ls;
    __syncthreads();
    float s = 0.f;
#pragma unroll
    for (int i = 0; i < 8; i++) s += sred[i];
    const float inv = 1.0f / s;

#pragma unroll
    for (int it = 0; it < 2; it++) {
        const int g = tid + it * 256;
        if (g < nv) {
            float4 v = x[it];
            *(float4*)(ap + g * 4) =
                make_float4(v.x * inv, v.y * inv, v.z * inv, v.w * inv);
        }
    }
}

// ---------------- column-sum partials per q-chunk (deterministic) ----------------
// NQCH=16 chunks of 128 q-rows each; ratio window == chunk 15 exactly.
__global__ void colpart_kernel()
{
    const int k = blockIdx.x * 256 + threadIdx.x;
    const int h = blockIdx.y;
    const int z = blockIdx.z;
    const int qlo = z * 128, qhi = qlo + 128;
    const int qs = (k > qlo) ? k : qlo;
    const bool rz = (z == NQCH - 1);
    float s = 0.f, r = 0.f;
    for (int b = 0; b < Bc; b++) {
        const float* ap = g_attn + ((size_t)(b * NHc + h)) * Sc * Sc;
        for (int q = qs; q < qhi; q++) {
            float a = ap[(size_t)q * Sc + k];
            s += a;
            if (rz && q >= Sc - MBc) r += a;
        }
    }
    g_colpart[((size_t)z * NHc + h) * Sc + k] = s;
    if (rz) g_ratio[h * Sc + k] = r;
}

__global__ void colsumfin_kernel()
{
    const int k = blockIdx.x * 256 + threadIdx.x;
    const int h = blockIdx.y;
    float s = 0.f;
#pragma unroll
    for (int z = 0; z < NQCH; z++) s += g_colpart[((size_t)z * NHc + h) * Sc + k];
    g_colsum[h * Sc + k] = s;
}

// ---------------- top-k per head (jax tie-break: lowest index) ----------------
__global__ __launch_bounds__(256) void topk_kernel()
{
    const int h = blockIdx.x, tid = threadIdx.x;
    __shared__ float tv[NCAND];
    __shared__ float rv[256];
    __shared__ int   ri[256];

    for (int i = tid; i < NCAND; i += 256) tv[i] = g_colsum[h * Sc + SBc + i];
    __syncthreads();

    for (int r = 0; r < TKc; r++) {
        float bv = -1e30f; int bi = NCAND;
        for (int i = tid; i < NCAND; i += 256) {
            float v = tv[i];
            if (v > bv) { bv = v; bi = i; }
        }
        rv[tid] = bv; ri[tid] = bi;
        __syncthreads();
        for (int st = 128; st > 0; st >>= 1) {
            if (tid < st) {
                if (rv[tid + st] > rv[tid] ||
                    (rv[tid + st] == rv[tid] && ri[tid + st] < ri[tid])) {
                    rv[tid] = rv[tid + st]; ri[tid] = ri[tid + st];
                }
            }
            __syncthreads();
        }
        if (tid == 0) {
            const int gi = ri[0] + SBc;
            g_topidx[h * TKc + r] = gi;
            g_topval[h * TKc + r] = g_ratio[h * Sc + gi] * (1.0f / MBc);
            tv[ri[0]] = -1e30f;
        }
        __syncthreads();
    }
}

// ---------------- v[b,h,SB,:] = sum_j v[b,h,idx_j,:] * val_j ----------------
__global__ void vupdate_kernel()
{
    const int bh = blockIdx.x;
    const int h  = bh % NHc;
    const int d  = threadIdx.x;
    float* vp = g_v + (size_t)bh * Sc * HDc;
    float acc = 0.f;
#pragma unroll
    for (int j = 0; j < TKc; j++)
        acc += vp[(size_t)g_topidx[h * TKc + j] * HDc + d] * g_topval[h * TKc + j];
    vp[(size_t)SBc * HDc + d] = acc;
}

// ================= out = attn @ v (TF32, causal, dbuf), scatter ==============
__global__ __launch_bounds__(256) void attnv_tc()
{
    __shared__ unsigned As[2][16][APAD]; // [k][m]
    __shared__ unsigned Vs[2][128][20];  // [n][k]

    const int tid = threadIdx.x, lane = tid & 31, w = tid >> 5;
    const int bh = blockIdx.y;
    const int bm = blockIdx.x * 128;
    const int wm = (w >> 2) * 64, wn = (w & 3) * 32;
    const int ar = lane >> 2, ak = lane & 3;

    const float* attn = g_attn + (size_t)bh * Sc * Sc;
    const float* vp   = g_v    + (size_t)bh * Sc * HDc;

    const int lrow = tid & 127, lkh = (tid >> 7) * 8;
    const int q_l = bm + lrow;
    const float* arow = attn + (size_t)q_l * Sc;
    const int vk = tid & 15, vn = (tid >> 4) * 8;

    float acc[4][4][4];
#pragma unroll
    for (int mt = 0; mt < 4; mt++)
#pragma unroll
        for (int nt = 0; nt < 4; nt++)
#pragma unroll
            for (int i = 0; i < 4; i++) acc[mt][nt][i] = 0.f;

    const int kend = bm + 128;

#define STS_A_MASKED(BUFI, V0, V1, KB)                                        \
    As[BUFI][lkh+0][lrow] = ((KB)+0 <= q_l) ? f2t(V0.x) : 0u;                 \
    As[BUFI][lkh+1][lrow] = ((KB)+1 <= q_l) ? f2t(V0.y) : 0u;                 \
    As[BUFI][lkh+2][lrow] = ((KB)+2 <= q_l) ? f2t(V0.z) : 0u;                 \
    As[BUFI][lkh+3][lrow] = ((KB)+3 <= q_l) ? f2t(V0.w) : 0u;                 \
    As[BUFI][lkh+4][lrow] = ((KB)+4 <= q_l) ? f2t(V1.x) : 0u;                 \
    As[BUFI][lkh+5][lrow] = ((KB)+5 <= q_l) ? f2t(V1.y) : 0u;                 \
    As[BUFI][lkh+6][lrow] = ((KB)+6 <= q_l) ? f2t(V1.z) : 0u;                 \
    As[BUFI][lkh+7][lrow] = ((KB)+7 <= q_l) ? f2t(V1.w) : 0u;

#define STS_V(BUFI, V0, V1)                                                   \
    Vs[BUFI][vn+0][vk]=f2t(V0.x); Vs[BUFI][vn+1][vk]=f2t(V0.y);               \
    Vs[BUFI][vn+2][vk]=f2t(V0.z); Vs[BUFI][vn+3][vk]=f2t(V0.w);               \
    Vs[BUFI][vn+4][vk]=f2t(V1.x); Vs[BUFI][vn+5][vk]=f2t(V1.y);               \
    Vs[BUFI][vn+6][vk]=f2t(V1.z); Vs[BUFI][vn+7][vk]=f2t(V1.w);

    // prologue: tile k0 = 0
    {
        float4 a0v = *(const float4*)(arow + lkh);
        float4 a1v = *(const float4*)(arow + lkh + 4);
        STS_A_MASKED(0, a0v, a1v, lkh);
        const float* vr = vp + (size_t)vk * HDc + vn;
        float4 v0 = *(const float4*)vr, v1 = *(const float4*)(vr + 4);
        STS_V(0, v0, v1);
    }
    __syncthreads();

    int buf = 0;
    for (int k0 = 0; k0 < kend; k0 += 16) {
        const bool more = (k0 + 16 < kend);
        float4 a0v, a1v, v0, v1;
        if (more) {
            a0v = *(const float4*)(arow + k0 + 16 + lkh);
            a1v = *(const float4*)(arow + k0 + 20 + lkh);
            const float* vr = vp + (size_t)(k0 + 16 + vk) * HDc + vn;
            v0 = *(const float4*)vr; v1 = *(const float4*)(vr + 4);
        }

#pragma unroll
        for (int ks = 0; ks < 16; ks += 8) {
            unsigned afr[4][4], bfr[4][2];
#pragma unroll
            for (int mt = 0; mt < 4; mt++) {
                const int m0 = wm + mt * 16 + ar;
                afr[mt][0] = As[buf][ks+ak][m0];
                afr[mt][1] = As[buf][ks+ak][m0+8];
                afr[mt][2] = As[buf][ks+4+ak][m0];
                afr[mt][3] = As[buf][ks+4+ak][m0+8];
            }
#pragma unroll
            for (int nt = 0; nt < 4; nt++) {
                const int n0 = wn + nt * 8 + ar;
                bfr[nt][0] = Vs[buf][n0][ks+ak];
                bfr[nt][1] = Vs[buf][n0][ks+4+ak];
            }
#pragma unroll
            for (int mt = 0; mt < 4; mt++)
#pragma unroll
                for (int nt = 0; nt < 4; nt++) mma8(acc[mt][nt], afr[mt], bfr[nt]);
        }

        if (more) {
            const int nb = buf ^ 1;
            const int kb2 = k0 + 16 + lkh;
            STS_A_MASKED(nb, a0v, a1v, kb2);
            STS_V(nb, v0, v1);
        }
        __syncthreads();
        buf ^= 1;
    }

    const int b = bh >> 4, h = bh & 15;
    const int ac2 = (lane & 3) * 2;
#pragma unroll
    for (int nt = 0; nt < 4; nt++) {
        const int col = h * HDc + wn + nt * 8 + ac2;
#pragma unroll
        for (int mt = 0; mt < 4; mt++) {
            const int q = bm + wm + mt * 16 + ar;
            *(float2*)&g_outh[((size_t)(b * Sc + q)) * HIDc + col] =
                make_float2(acc[mt][nt][0], acc[mt][nt][1]);
            *(float2*)&g_outh[((size_t)(b * Sc + q + 8)) * HIDc + col] =
                make_float2(acc[mt][nt][2], acc[mt][nt][3]);
        }
    }
#undef STS_A_MASKED
#undef STS_V
}

// ---------------- launch ----------------
extern "C" void kernel_launch(void* const* d_in, const int* in_sizes, int n_in,
                              void* d_out, int out_size)
{
    (void)in_sizes; (void)n_in; (void)out_size;
    const float* hs    = (const float*)d_in[0];
    const float* amask = (const float*)d_in[1];
    const int*   pos   = (const int*)  d_in[2];
    const float* Wqkv  = (const float*)d_in[3];
    const float* bqkv  = (const float*)d_in[4];
    const float* Wd    = (const float*)d_in[5];
    const float* bd    = (const float*)d_in[6];
    float* out = (float*)d_out;

    void *p_q = nullptr, *p_k = nullptr, *p_v = nullptr, *p_outh = nullptr;
    cudaGetSymbolAddress(&p_q, g_q);
    cudaGetSymbolAddress(&p_k, g_k);
    cudaGetSymbolAddress(&p_v, g_v);
    cudaGetSymbolAddress(&p_outh, g_outh);

    cudaFuncSetAttribute(qkv_gemm_tc,
                         cudaFuncAttributeMaxDynamicSharedMemorySize, SMEMDYN);
    cudaFuncSetAttribute(gemm_tn_tc256,
                         cudaFuncAttributeMaxDynamicSharedMemorySize, SMEMDYN);

    // 1. QKV projection + per-head scatter (TF32, 128x256, dbuf)
    qkv_gemm_tc<<<dim3(3 * HIDc / 256, (Bc * Sc) / 128), 256, SMEMDYN>>>(
        hs, Wqkv, bqkv, (float*)p_q, (float*)p_k, (float*)p_v);

    // 2. RoPE in place on rotary dims
    rope_inplace<<<dim3(Sc, NHc, Bc), 64>>>(pos);

    // 3. scaled QK^T (causal tiles, TF32, dbuf)
    scores_tc<<<dim3(Sc / 128, Sc / 128, Bc * NHc), 256>>>();

    // 4. row softmax (vectorized, causal groups only)
    softmax_kernel<<<Bc * NHc * Sc, 256>>>(amask);

    // 5a/5b. column statistics: per-chunk partials + fixed-order sum
    colpart_kernel<<<dim3(Sc / 256, NHc, NQCH), 256>>>();
    colsumfin_kernel<<<dim3(Sc / 256, NHc), 256>>>();

    // 6. per-head top-16
    topk_kernel<<<NHc, 256>>>();

    // 7. merged row write into v
    vupdate_kernel<<<Bc * NHc, HDc>>>();

    // 8. attn @ v (TF32, dbuf)
    attnv_tc<<<dim3(Sc / 128, Bc * NHc), 256>>>();

    // 9. dense projection (TF32, 128x256, dbuf)
    gemm_tn_tc256<<<dim3(HIDc / 256, (Bc * Sc) / 128), 256, SMEMDYN>>>(
        (const float*)p_outh, Wd, bd, out, Bc * Sc, HIDc, HIDc);
}